// round 15
// baseline (speedup 1.0000x reference)
#include <cuda_runtime.h>
#include <cstdint>

#define ALPHA 0.9048374180359595f   // exp(-1/10), rounds to same f32 as JAX
#define BT 12800                     // B*T = 128*100

typedef unsigned long long u64;

// Layer-1 pooled conv output, layout [sample = b*100+t][256 = c*64+y*8+x]
__device__ float g_h1[BT * 256];

// ---- f32x2 packed-math helpers (sm_10x) -----------------------------------
__device__ __forceinline__ u64 pack2(float a, float b) {
    u64 r; asm("mov.b64 %0, {%1,%2};" : "=l"(r) : "f"(a), "f"(b)); return r;
}
__device__ __forceinline__ void unpack2(u64 v, float& a, float& b) {
    asm("mov.b64 {%0,%1}, %2;" : "=f"(a), "=f"(b) : "l"(v));
}
__device__ __forceinline__ u64 fma2(u64 a, u64 b, u64 c) {
    u64 r; asm("fma.rn.f32x2 %0, %1, %2, %3;" : "=l"(r) : "l"(a), "l"(b), "l"(c));
    return r;
}
__device__ __forceinline__ u64 add2(u64 a, u64 b) {
    u64 r; asm("add.rn.f32x2 %0, %1, %2;" : "=l"(r) : "l"(a), "l"(b)); return r;
}

// ---------------------------------------------------------------------------
// Stage 1: folded conv1(5x5,pad2)+pool4 as 8x8 stride-4 conv, f32x2 FMAs.
// 4 samples/block, 256 threads: thread = (sl, pos->(py,px)), all 4 channels.
// Channel pairs packed: wA[tap]={c0,c1}, wB[tap]={c2,c3} (u64 f32x2).
// smem (q,r)-split layout keeps stride-4 reads conflict-free.
// ---------------------------------------------------------------------------
__global__ void __launch_bounds__(256) k_stage1(const float* __restrict__ x,
                                                const float* __restrict__ w1) {
    __shared__ float xs[4][2][4][36][10];   // 11520 floats = 46 KB
    __shared__ u64 wA[128], wB[128];        // [(ic*8+dy)*8+dx]
    int tid = threadIdx.x;

    // fold conv1+pool weights: thread tid -> (tap = tid>>1, half = tid&1)
    {
        int tap = tid >> 1, half = tid & 1;
        int dx = tap & 7, dy = (tap >> 3) & 7, ic = tap >> 6;
        int iy0 = dy > 3 ? dy - 3 : 0, iy1 = dy < 4 ? dy : 4;
        int ix0 = dx > 3 ? dx - 3 : 0, ix1 = dx < 4 ? dx : 4;
        float s0 = 0.f, s1 = 0.f;
        for (int iy = iy0; iy <= iy1; iy++)
            for (int ix = ix0; ix <= ix1; ix++) {
                s0 += w1[(((2 * half + 0) * 2 + ic) * 5 + iy) * 5 + ix];
                s1 += w1[(((2 * half + 1) * 2 + ic) * 5 + iy) * 5 + ix];
            }
        u64 p = pack2(s0 * (1.0f / 16.0f), s1 * (1.0f / 16.0f));
        if (half) wB[tap] = p; else wA[tap] = p;
    }
    float* xsf = (float*)xs;
    for (int idx = tid; idx < 11520; idx += 256) xsf[idx] = 0.f;
    __syncthreads();

    // load 4 samples (8192 floats) coalesced; scatter conflict-free
    const float* xg = x + (size_t)blockIdx.x * 8192;
#pragma unroll
    for (int k = 0; k < 32; k++) {
        int idx = tid + k * 256;
        int sl = idx >> 11, rem = idx & 2047;
        int ic = rem >> 10, yy = (rem >> 5) & 31, cc = rem & 31;
        xs[sl][ic][cc & 3][yy + 2][(cc >> 2) + 1] = xg[idx];
    }
    __syncthreads();

    int sl = tid >> 6, pos = tid & 63, py = pos >> 3, px = pos & 7;
    u64 accA = 0ull, accB = 0ull;           // {a0,a1}, {a2,a3}
#pragma unroll
    for (int ic = 0; ic < 2; ic++)
#pragma unroll
        for (int dy = 0; dy < 8; dy++) {
            int row = 4 * py + dy;
#pragma unroll
            for (int dx = 0; dx < 8; dx++) {
                int u = 4 * px + dx + 2;              // col+4 encoding
                float xv = xs[sl][ic][u & 3][row][u >> 2];
                u64 xx = pack2(xv, xv);
                int tap = (ic * 8 + dy) * 8 + dx;
                accA = fma2(xx, wA[tap], accA);       // two fmaf, bit-exact
                accB = fma2(xx, wB[tap], accB);
            }
        }
    float a0, a1, a2, a3;
    unpack2(accA, a0, a1);
    unpack2(accB, a2, a3);
    size_t s = (size_t)blockIdx.x * 4 + sl;
    g_h1[s * 256 +   0 + pos] = a0;
    g_h1[s * 256 +  64 + pos] = a1;
    g_h1[s * 256 + 128 + pos] = a2;
    g_h1[s * 256 + 192 + pos] = a3;
}

// ---------------------------------------------------------------------------
// Stages 2-5 fused, ONE WARP PER BATCH — no barriers, all exchange via ballot.
// Lane l owns layer-1 neurons f = 32j+l (j=0..7): 8 ballots rebuild all 256
// spike bits in every lane (word j = neurons 32j..32j+31, bit = lane).
// Conv lanes own outputs o = 32k+l (k=0..3): c2 = 2k+(l>>4), y2/x2 fixed per
// lane, so the 16 nibbles are shared across k and the LUT is float4 over k:
//   lutc[(l>>4)*256 + (ic*4+dy)*16 + nib] = {val(c2=h), val(2+h), val(4+h), val(6+h)}
// accumulated with packed f32x2 adds. Layer-2 spikes -> 4 ballots -> sbits;
// linear [2,128] deferred post-loop via a second nibble LUT (packed {o0,o1}).
// ---------------------------------------------------------------------------
__global__ void __launch_bounds__(32) k_scan(const float* __restrict__ w2,
                                             const float* __restrict__ lin_w,
                                             float* __restrict__ out) {
    __shared__ float4 lutc[512];        // [h][ic*4+dy][nib] -> float4 over k
    __shared__ u64 lutl[512];           // [w8*8+np][nib] -> {sum lw0, sum lw1}
    __shared__ uint32_t sbits[100][4];  // layer-2 spike words per step
    int lane = threadIdx.x;
    int b = blockIdx.x;

    // Build conv LUT (16 entries/lane)
    for (int e = lane; e < 512; e += 32) {
        int nib = e & 15, rowi = e >> 4;            // rowi = h*16 + ic*4 + dy
        int dy = rowi & 3, ic = (rowi >> 2) & 3, h = rowi >> 4;
        float4 v;
        float* vp = (float*)&v;
        for (int k = 0; k < 4; k++) {
            int c2 = 2 * k + h;
            float s = 0.f;
            for (int dx = 0; dx < 4; dx++)
                if (nib >> dx & 1) {
                    int iy0 = dy > 1 ? dy - 1 : 0, iy1 = dy < 2 ? dy : 2;
                    int ix0 = dx > 1 ? dx - 1 : 0, ix1 = dx < 2 ? dx : 2;
                    for (int iy = iy0; iy <= iy1; iy++)
                        for (int ix = ix0; ix <= ix1; ix++)
                            s += w2[((c2 * 4 + ic) * 3 + iy) * 3 + ix];
                }
            vp[k] = s * 0.25f;
        }
        lutc[e] = v;
    }
    // Build linear LUT (16 entries/lane): f = w8*32 + np*4 + dx
    for (int e = lane; e < 512; e += 32) {
        int nib = e & 15, posi = e >> 4;            // posi = w8*8 + np
        int w8 = posi >> 3, np = posi & 7;
        float s0 = 0.f, s1 = 0.f;
        for (int dx = 0; dx < 4; dx++)
            if (nib >> dx & 1) {
                int f = w8 * 32 + np * 4 + dx;
                s0 += lin_w[f];
                s1 += lin_w[128 + f];
            }
        lutl[e] = pack2(s0, s1);
    }
    __syncwarp();

    int y2 = (lane >> 2) & 3, x2 = lane & 3, hh = lane >> 4, xsh = 2 * x2;
    const float4* lc = lutc + hh * 256;

    float v1m[8], v1u[8], h[8], hn[8];
    float v2m0 = 0.f, v2m1 = 0.f, v2m2 = 0.f, v2m3 = 0.f;
    float v2u0 = 0.f, v2u1 = 0.f, v2u2 = 0.f, v2u3 = 0.f;
#pragma unroll
    for (int j = 0; j < 8; j++) { v1m[j] = 0.f; v1u[j] = 0.f; }

    const float* hp = g_h1 + (size_t)b * 25600;
#pragma unroll
    for (int j = 0; j < 8; j++) hn[j] = hp[32 * j + lane];

    for (int t = 0; t < 100; t++) {
#pragma unroll
        for (int j = 0; j < 8; j++) h[j] = hn[j];
        if (t < 99) {
            const float* hq = hp + (t + 1) * 256 + lane;
#pragma unroll
            for (int j = 0; j < 8; j++) hn[j] = hq[32 * j];
        }

        // layer-1 exp_leak + LIF, 8 neurons/lane; ballots rebuild spike words
        uint32_t m[8];
#pragma unroll
        for (int j = 0; j < 8; j++) {
            v1m[j] = fmaf(ALPHA, v1m[j], h[j]);
            v1u[j] = fmaf(ALPHA, v1u[j], v1m[j]);
            bool s1 = (v1u[j] >= 1.0f);
            v1u[j] -= s1 ? 1.0f : 0.0f;
            m[j] = __ballot_sync(0xffffffffu, s1);
        }

        // bitwise folded conv2+pool2, float4-LUT over k, packed adds
        u64 a01 = 0ull, a23 = 0ull;
#pragma unroll
        for (int dy = 0; dy < 4; dy++) {
            int r = 2 * y2 - 1 + dy;
            bool hv = ((unsigned)r < 8u);
            bool hb = (r & 4) != 0;
            int rsh = (r & 3) * 8;
#pragma unroll
            for (int ic = 0; ic < 4; ic++) {
                uint32_t v = hb ? m[2 * ic + 1] : m[2 * ic];   // static idx, SEL
                uint32_t rb = hv ? ((v >> rsh) & 0xFFu) : 0u;
                uint32_t nib = ((rb << 1) >> xsh) & 15u;
                float4 w4 = lc[(ic * 4 + dy) * 16 + nib];
                a01 = add2(a01, pack2(w4.x, w4.y));
                a23 = add2(a23, pack2(w4.z, w4.w));
            }
        }
        float a0, a1, a2, a3;
        unpack2(a01, a0, a1);
        unpack2(a23, a2, a3);

        // layer-2 exp_leak + LIF for the lane's 4 outputs (o = 32k + lane)
        v2m0 = fmaf(ALPHA, v2m0, a0); v2u0 = fmaf(ALPHA, v2u0, v2m0);
        v2m1 = fmaf(ALPHA, v2m1, a1); v2u1 = fmaf(ALPHA, v2u1, v2m1);
        v2m2 = fmaf(ALPHA, v2m2, a2); v2u2 = fmaf(ALPHA, v2u2, v2m2);
        v2m3 = fmaf(ALPHA, v2m3, a3); v2u3 = fmaf(ALPHA, v2u3, v2m3);
        bool s20 = (v2u0 >= 1.0f); v2u0 -= s20 ? 1.0f : 0.0f;
        bool s21 = (v2u1 >= 1.0f); v2u1 -= s21 ? 1.0f : 0.0f;
        bool s22 = (v2u2 >= 1.0f); v2u2 -= s22 ? 1.0f : 0.0f;
        bool s23 = (v2u3 >= 1.0f); v2u3 -= s23 ? 1.0f : 0.0f;
        uint32_t q0 = __ballot_sync(0xffffffffu, s20);
        uint32_t q1 = __ballot_sync(0xffffffffu, s21);
        uint32_t q2 = __ballot_sync(0xffffffffu, s22);
        uint32_t q3 = __ballot_sync(0xffffffffu, s23);
        if (lane == 0) {
            sbits[t][0] = q0; sbits[t][1] = q1;
            sbits[t][2] = q2; sbits[t][3] = q3;
        }
    }
    __syncwarp();

    // Deferred linear via nibble LUT: out[b,t,o] = sum_f lw[o,f]*spike[t,f]
#pragma unroll
    for (int base = 0; base < 128; base += 32) {
        int t = base + lane;
        if (t < 100) {
            uint32_t s0 = sbits[t][0], s1 = sbits[t][1],
                     s2 = sbits[t][2], s3 = sbits[t][3];
            u64 acc = 0ull;
#pragma unroll
            for (int np = 0; np < 8; np++) {
                acc = add2(acc, lutl[(0 * 8 + np) * 16 + ((s0 >> (4 * np)) & 15u)]);
            }
#pragma unroll
            for (int np = 0; np < 8; np++) {
                acc = add2(acc, lutl[(1 * 8 + np) * 16 + ((s1 >> (4 * np)) & 15u)]);
            }
#pragma unroll
            for (int np = 0; np < 8; np++) {
                acc = add2(acc, lutl[(2 * 8 + np) * 16 + ((s2 >> (4 * np)) & 15u)]);
            }
#pragma unroll
            for (int np = 0; np < 8; np++) {
                acc = add2(acc, lutl[(3 * 8 + np) * 16 + ((s3 >> (4 * np)) & 15u)]);
            }
            float o0, o1;
            unpack2(acc, o0, o1);
            float2 ov = {o0, o1};
            *(float2*)(out + (size_t)(b * 100 + t) * 2) = ov;
        }
    }
}

// ---------------------------------------------------------------------------
extern "C" void kernel_launch(void* const* d_in, const int* in_sizes, int n_in,
                              void* d_out, int out_size) {
    // Rank-based input binding: invariant to metadata ordering AND units.
    int xi = 0;
    for (int i = 1; i < n_in; i++)
        if (in_sizes[i] > in_sizes[xi]) xi = i;

    int rest[3]; int nr = 0;
    for (int i = 0; i < n_in && nr < 3; i++)
        if (i != xi) rest[nr++] = i;
    for (int a = 0; a < 2; a++)
        for (int bq = 0; bq < 2 - a; bq++)
            if (in_sizes[rest[bq]] > in_sizes[rest[bq + 1]]) {
                int tmp = rest[bq]; rest[bq] = rest[bq + 1]; rest[bq + 1] = tmp;
            }

    const float* x  = (const float*)d_in[xi];       // [128,100,2,32,32]
    const float* w1 = (const float*)d_in[rest[0]];  // [4,2,5,5]   (200)
    const float* lw = (const float*)d_in[rest[1]];  // [2,128]     (256)
    const float* w2 = (const float*)d_in[rest[2]];  // [8,4,3,3]   (288)
    float* out = (float*)d_out;                     // [128,100,2]

    k_stage1<<<3200, 256>>>(x, w1);
    k_scan<<<128, 32>>>(w2, lw, out);
}

// round 17
// speedup vs baseline: 1.7495x; 1.7495x over previous
#include <cuda_runtime.h>
#include <cstdint>

#define ALPHA 0.9048374180359595f   // exp(-1/10), rounds to same f32 as JAX
#define BT 12800                     // B*T = 128*100

typedef unsigned long long u64;

// Layer-1 pooled conv output, layout [sample = b*100+t][256 = c*64+y*8+x]
__device__ float g_h1[BT * 256];

// ---- f32x2 packed-math helpers (sm_10x) -----------------------------------
__device__ __forceinline__ u64 pack2(float a, float b) {
    u64 r; asm("mov.b64 %0, {%1,%2};" : "=l"(r) : "f"(a), "f"(b)); return r;
}
__device__ __forceinline__ void unpack2(u64 v, float& a, float& b) {
    asm("mov.b64 {%0,%1}, %2;" : "=f"(a), "=f"(b) : "l"(v));
}
__device__ __forceinline__ u64 fma2(u64 a, u64 b, u64 c) {
    u64 r; asm("fma.rn.f32x2 %0, %1, %2, %3;" : "=l"(r) : "l"(a), "l"(b), "l"(c));
    return r;
}
__device__ __forceinline__ u64 add2(u64 a, u64 b) {
    u64 r; asm("add.rn.f32x2 %0, %1, %2;" : "=l"(r) : "l"(a), "l"(b)); return r;
}

// ---------------------------------------------------------------------------
// Stage 1 (unchanged from round 15: measured 51.3us): folded conv1+pool4 as
// 8x8 stride-4 conv, f32x2 packed FMAs, 4 samples/block.
// ---------------------------------------------------------------------------
__global__ void __launch_bounds__(256) k_stage1(const float* __restrict__ x,
                                                const float* __restrict__ w1) {
    __shared__ float xs[4][2][4][36][10];   // 11520 floats = 46 KB
    __shared__ u64 wA[128], wB[128];        // [(ic*8+dy)*8+dx]
    int tid = threadIdx.x;

    {
        int tap = tid >> 1, half = tid & 1;
        int dx = tap & 7, dy = (tap >> 3) & 7, ic = tap >> 6;
        int iy0 = dy > 3 ? dy - 3 : 0, iy1 = dy < 4 ? dy : 4;
        int ix0 = dx > 3 ? dx - 3 : 0, ix1 = dx < 4 ? dx : 4;
        float s0 = 0.f, s1 = 0.f;
        for (int iy = iy0; iy <= iy1; iy++)
            for (int ix = ix0; ix <= ix1; ix++) {
                s0 += w1[(((2 * half + 0) * 2 + ic) * 5 + iy) * 5 + ix];
                s1 += w1[(((2 * half + 1) * 2 + ic) * 5 + iy) * 5 + ix];
            }
        u64 p = pack2(s0 * (1.0f / 16.0f), s1 * (1.0f / 16.0f));
        if (half) wB[tap] = p; else wA[tap] = p;
    }
    float* xsf = (float*)xs;
    for (int idx = tid; idx < 11520; idx += 256) xsf[idx] = 0.f;
    __syncthreads();

    const float* xg = x + (size_t)blockIdx.x * 8192;
#pragma unroll
    for (int k = 0; k < 32; k++) {
        int idx = tid + k * 256;
        int sl = idx >> 11, rem = idx & 2047;
        int ic = rem >> 10, yy = (rem >> 5) & 31, cc = rem & 31;
        xs[sl][ic][cc & 3][yy + 2][(cc >> 2) + 1] = xg[idx];
    }
    __syncthreads();

    int sl = tid >> 6, pos = tid & 63, py = pos >> 3, px = pos & 7;
    u64 accA = 0ull, accB = 0ull;
#pragma unroll
    for (int ic = 0; ic < 2; ic++)
#pragma unroll
        for (int dy = 0; dy < 8; dy++) {
            int row = 4 * py + dy;
#pragma unroll
            for (int dx = 0; dx < 8; dx++) {
                int u = 4 * px + dx + 2;
                float xv = xs[sl][ic][u & 3][row][u >> 2];
                u64 xx = pack2(xv, xv);
                int tap = (ic * 8 + dy) * 8 + dx;
                accA = fma2(xx, wA[tap], accA);
                accB = fma2(xx, wB[tap], accB);
            }
        }
    float a0, a1, a2, a3;
    unpack2(accA, a0, a1);
    unpack2(accB, a2, a3);
    size_t s = (size_t)blockIdx.x * 4 + sl;
    g_h1[s * 256 +   0 + pos] = a0;
    g_h1[s * 256 +  64 + pos] = a1;
    g_h1[s * 256 + 128 + pos] = a2;
    g_h1[s * 256 + 192 + pos] = a3;
}

// ---------------------------------------------------------------------------
// Stages 2-5, PHASED: block = one batch, 256 threads, 3 barriers TOTAL.
//  A: 8 warps x 32 private layer-1 LIF scans; ballots -> swords[100][8].
//  B: 8 warps t-strided bitwise conv2 (float4 nibble LUT) -> acc[100][128].
//  C: 4 warps private layer-2 LIF scans from acc; ballots -> sbits[100][4].
//  D: deferred linear via nibble LUT.
// All arithmetic orders identical to round 15 => identical spikes.
// ---------------------------------------------------------------------------
#define SC_SMEM 68288

__global__ void __launch_bounds__(256) k_scan(const float* __restrict__ w2,
                                              const float* __restrict__ lin_w,
                                              float* __restrict__ out) {
    extern __shared__ unsigned char smraw[];
    float4*   lutc   = (float4*)smraw;                    // 512 * 16 = 8192
    u64*      lutl   = (u64*)(smraw + 8192);              // 512 * 8  = 4096
    float*    acc    = (float*)(smraw + 12288);           // 100*128*4= 51200
    uint32_t* swords = (uint32_t*)(smraw + 63488);        // 100*8*4  = 3200
    uint32_t* sbits  = (uint32_t*)(smraw + 66688);        // 100*4*4  = 1600

    int tid = threadIdx.x;
    int lane = tid & 31, w = tid >> 5;
    int b = blockIdx.x;

    // Build conv LUT: lutc[h*256 + (ic*4+dy)*16 + nib] = float4 over k (c2=2k+h)
    for (int e = tid; e < 512; e += 256) {
        int nib = e & 15, rowi = e >> 4;
        int dy = rowi & 3, ic = (rowi >> 2) & 3, h = rowi >> 4;
        float4 v;
        float* vp = (float*)&v;
        for (int k = 0; k < 4; k++) {
            int c2 = 2 * k + h;
            float s = 0.f;
            for (int dx = 0; dx < 4; dx++)
                if (nib >> dx & 1) {
                    int iy0 = dy > 1 ? dy - 1 : 0, iy1 = dy < 2 ? dy : 2;
                    int ix0 = dx > 1 ? dx - 1 : 0, ix1 = dx < 2 ? dx : 2;
                    for (int iy = iy0; iy <= iy1; iy++)
                        for (int ix = ix0; ix <= ix1; ix++)
                            s += w2[((c2 * 4 + ic) * 3 + iy) * 3 + ix];
                }
            vp[k] = s * 0.25f;
        }
        lutc[e] = v;
    }
    // Linear LUT: lutl[(w8*8+np)*16 + nib] = {sum lw0, sum lw1}, f = w8*32+np*4+dx
    for (int e = tid; e < 512; e += 256) {
        int nib = e & 15, posi = e >> 4;
        int w8 = posi >> 3, np = posi & 7;
        float s0 = 0.f, s1 = 0.f;
        for (int dx = 0; dx < 4; dx++)
            if (nib >> dx & 1) {
                int f = w8 * 32 + np * 4 + dx;
                s0 += lin_w[f];
                s1 += lin_w[128 + f];
            }
        lutl[e] = pack2(s0, s1);
    }

    // ---- Phase A: layer-1 LIF, warp w owns neurons f = 32w + lane ----------
    {
        const float* hp = g_h1 + (size_t)b * 25600 + w * 32 + lane;
        float v1m = 0.f, v1u = 0.f;
        float hbuf[4];
#pragma unroll
        for (int d = 0; d < 4; d++) hbuf[d] = hp[d * 256];
        for (int t0 = 0; t0 < 100; t0 += 4) {
#pragma unroll
            for (int d = 0; d < 4; d++) {
                int t = t0 + d;
                float h = hbuf[d];
                if (t + 4 < 100) hbuf[d] = hp[(t + 4) * 256];
                v1m = fmaf(ALPHA, v1m, h);
                v1u = fmaf(ALPHA, v1u, v1m);
                bool s1 = (v1u >= 1.0f);
                v1u -= s1 ? 1.0f : 0.0f;
                uint32_t mm = __ballot_sync(0xffffffffu, s1);  // off-chain
                if (lane == 0) swords[t * 8 + w] = mm;
            }
        }
    }
    __syncthreads();

    // ---- Phase B: bitwise conv2, warp w handles t = w, w+8, ... ------------
    {
        int y2 = (lane >> 2) & 3, x2 = lane & 3, hh = lane >> 4, xsh = 2 * x2;
        const float4* lc = lutc + hh * 256;
        for (int t = w; t < 100; t += 8) {
            uint4 wa = *(const uint4*)&swords[t * 8 + 0];
            uint4 wb = *(const uint4*)&swords[t * 8 + 4];
            uint32_t m0 = wa.x, m1 = wa.y, m2 = wa.z, m3 = wa.w;
            uint32_t m4 = wb.x, m5 = wb.y, m6 = wb.z, m7 = wb.w;
            u64 a01 = 0ull, a23 = 0ull;
#pragma unroll
            for (int dy = 0; dy < 4; dy++) {
                int r = 2 * y2 - 1 + dy;
                bool hv = ((unsigned)r < 8u);
                bool hb = (r & 4) != 0;
                int rsh = (r & 3) * 8;
                uint32_t v0 = hb ? m1 : m0;
                uint32_t v1 = hb ? m3 : m2;
                uint32_t v2 = hb ? m5 : m4;
                uint32_t v3 = hb ? m7 : m6;
                uint32_t b0 = hv ? ((v0 >> rsh) & 0xFFu) : 0u;
                uint32_t b1 = hv ? ((v1 >> rsh) & 0xFFu) : 0u;
                uint32_t b2 = hv ? ((v2 >> rsh) & 0xFFu) : 0u;
                uint32_t b3 = hv ? ((v3 >> rsh) & 0xFFu) : 0u;
                uint32_t n0 = ((b0 << 1) >> xsh) & 15u;
                uint32_t n1 = ((b1 << 1) >> xsh) & 15u;
                uint32_t n2 = ((b2 << 1) >> xsh) & 15u;
                uint32_t n3 = ((b3 << 1) >> xsh) & 15u;
                float4 w40 = lc[(0 * 4 + dy) * 16 + n0];
                float4 w41 = lc[(1 * 4 + dy) * 16 + n1];
                float4 w42 = lc[(2 * 4 + dy) * 16 + n2];
                float4 w43 = lc[(3 * 4 + dy) * 16 + n3];
                a01 = add2(a01, pack2(w40.x, w40.y));
                a23 = add2(a23, pack2(w40.z, w40.w));
                a01 = add2(a01, pack2(w41.x, w41.y));
                a23 = add2(a23, pack2(w41.z, w41.w));
                a01 = add2(a01, pack2(w42.x, w42.y));
                a23 = add2(a23, pack2(w42.z, w42.w));
                a01 = add2(a01, pack2(w43.x, w43.y));
                a23 = add2(a23, pack2(w43.z, w43.w));
            }
            float a0, a1, a2, a3;
            unpack2(a01, a0, a1);
            unpack2(a23, a2, a3);
            acc[t * 128 +  0 + lane] = a0;   // o = 32k + lane, c2 = 2k + (lane>>4)
            acc[t * 128 + 32 + lane] = a1;
            acc[t * 128 + 64 + lane] = a2;
            acc[t * 128 + 96 + lane] = a3;
        }
    }
    __syncthreads();

    // ---- Phase C: layer-2 LIF, warps 0-3, o = 32w + lane -------------------
    if (w < 4) {
        const float* ap = acc + w * 32 + lane;
        float v2m = 0.f, v2u = 0.f;
        float abuf[2];
        abuf[0] = ap[0];
        abuf[1] = ap[128];
        for (int t0 = 0; t0 < 100; t0 += 2) {
#pragma unroll
            for (int d = 0; d < 2; d++) {
                int t = t0 + d;
                float a = abuf[d];
                if (t + 2 < 100) abuf[d] = ap[(t + 2) * 128];
                v2m = fmaf(ALPHA, v2m, a);
                v2u = fmaf(ALPHA, v2u, v2m);
                bool s2 = (v2u >= 1.0f);
                v2u -= s2 ? 1.0f : 0.0f;
                uint32_t q = __ballot_sync(0xffffffffu, s2);   // off-chain
                if (lane == 0) sbits[t * 4 + w] = q;
            }
        }
    }
    __syncthreads();

    // ---- Phase D: deferred linear via nibble LUT ---------------------------
    if (tid < 200) {
        int t = tid >> 1, oo = tid & 1;
        uint32_t s0 = sbits[t * 4 + 0], s1 = sbits[t * 4 + 1],
                 s2 = sbits[t * 4 + 2], s3 = sbits[t * 4 + 3];
        u64 a = 0ull;
#pragma unroll
        for (int np = 0; np < 8; np++)
            a = add2(a, lutl[(0 * 8 + np) * 16 + ((s0 >> (4 * np)) & 15u)]);
#pragma unroll
        for (int np = 0; np < 8; np++)
            a = add2(a, lutl[(1 * 8 + np) * 16 + ((s1 >> (4 * np)) & 15u)]);
#pragma unroll
        for (int np = 0; np < 8; np++)
            a = add2(a, lutl[(2 * 8 + np) * 16 + ((s2 >> (4 * np)) & 15u)]);
#pragma unroll
        for (int np = 0; np < 8; np++)
            a = add2(a, lutl[(3 * 8 + np) * 16 + ((s3 >> (4 * np)) & 15u)]);
        float o0, o1;
        unpack2(a, o0, o1);
        out[(b * 100 + t) * 2 + oo] = oo ? o1 : o0;
    }
}

// ---------------------------------------------------------------------------
extern "C" void kernel_launch(void* const* d_in, const int* in_sizes, int n_in,
                              void* d_out, int out_size) {
    // Rank-based input binding: invariant to metadata ordering AND units.
    int xi = 0;
    for (int i = 1; i < n_in; i++)
        if (in_sizes[i] > in_sizes[xi]) xi = i;

    int rest[3]; int nr = 0;
    for (int i = 0; i < n_in && nr < 3; i++)
        if (i != xi) rest[nr++] = i;
    for (int a = 0; a < 2; a++)
        for (int bq = 0; bq < 2 - a; bq++)
            if (in_sizes[rest[bq]] > in_sizes[rest[bq + 1]]) {
                int tmp = rest[bq]; rest[bq] = rest[bq + 1]; rest[bq + 1] = tmp;
            }

    const float* x  = (const float*)d_in[xi];       // [128,100,2,32,32]
    const float* w1 = (const float*)d_in[rest[0]];  // [4,2,5,5]   (200)
    const float* lw = (const float*)d_in[rest[1]];  // [2,128]     (256)
    const float* w2 = (const float*)d_in[rest[2]];  // [8,4,3,3]   (288)
    float* out = (float*)d_out;                     // [128,100,2]

    cudaFuncSetAttribute(k_scan, cudaFuncAttributeMaxDynamicSharedMemorySize,
                         SC_SMEM);
    k_stage1<<<3200, 256>>>(x, w1);
    k_scan<<<128, 256, SC_SMEM>>>(w2, lw, out);
}